// round 1
// baseline (speedup 1.0000x reference)
#include <cuda_runtime.h>

#define BS 32
#define NA 8400
#define NC 80
#define NG 48
#define TK 13
#define EPSF 1e-9f

// output layout (floats), concatenated in reference return order
#define OFF_LAB 0
#define OFF_BOX (BS*NA)                 // 268800
#define OFF_SCR (OFF_BOX + BS*NA*4)     // 1344000
#define OFF_FG  (OFF_SCR + BS*NA*NC)    // 22848000
#define OFF_TGT (OFF_FG + BS*NA)        // 23116800

// scratch (device globals; allocation inside kernel_launch is forbidden)
__device__ float    g_metrics[BS*NG*NA];     // 51.6 MB
__device__ int      g_tk_idx[BS*NG*TK];
__device__ float    g_tk_align[BS*NG*TK];
__device__ float    g_tk_ovl[BS*NG*TK];
__device__ int      g_count[BS*NA];
__device__ int      g_cand_n[BS*NA];
__device__ float    g_cand_align[BS*NA];
__device__ float    g_cand_ovl[BS*NA];
__device__ unsigned g_pos_align[BS*NG];
__device__ unsigned g_pos_ovl[BS*NG];
__device__ float    g_norm[BS*NA];
__device__ int      g_labsel[BS*NA];

__device__ __forceinline__ float iou_f(float4 g, float garea, float4 p, float parea) {
    float iw = fminf(g.z, p.z) - fmaxf(g.x, p.x); iw = fmaxf(iw, 0.f);
    float ih = fminf(g.w, p.w) - fmaxf(g.y, p.y); ih = fmaxf(ih, 0.f);
    float inter = iw * ih;
    float uni = garea + parea - inter + EPSF;
    return inter / uni;   // >= 0 always, matches ref .clip(0)
}

// ---------------------------------------------------------------------------
// 1) fused: gather per-(b,n) class score + IoU^6 + in-gts mask -> g_metrics
//    block = (b, 128-anchor tile); score tile staged in smem (pad 84 to kill
//    the 16-way bank conflict of the raw 80-float stride).
// ---------------------------------------------------------------------------
__global__ void k_metric(const float* __restrict__ pd_scores,
                         const float4* __restrict__ pd_bbox,
                         const float2* __restrict__ anc,
                         const int* __restrict__ gt_labels,
                         const float4* __restrict__ gt_bbox) {
    __shared__ float  s_sc[128*84];
    __shared__ float4 s_pd[128];
    __shared__ float2 s_anc[128];
    __shared__ float4 s_gt[NG];
    __shared__ float  s_ga[NG];
    __shared__ int    s_lab[NG];

    int b  = blockIdx.y;
    int a0 = blockIdx.x * 128;
    int na = min(128, NA - a0);
    int tid = threadIdx.x;

    if (tid < NG) {
        float4 g = gt_bbox[b*NG + tid];
        s_gt[tid]  = g;
        s_ga[tid]  = (g.z - g.x) * (g.w - g.y + EPSF);
        s_lab[tid] = gt_labels[b*NG + tid];
    }
    for (int i = tid; i < na; i += 256) {
        s_pd[i]  = pd_bbox[b*NA + a0 + i];
        s_anc[i] = anc[a0 + i];
    }
    const float4* src4 = (const float4*)pd_scores + ((long)b*NA + a0) * (NC/4);
    int tot4 = na * (NC/4);
    for (int i4 = tid; i4 < tot4; i4 += 256) {
        int r = i4 / 20, c = i4 % 20;
        float4 v = src4[i4];
        *(float4*)&s_sc[r*84 + c*4] = v;
    }
    __syncthreads();

    for (int j = tid; j < NG*128; j += 256) {
        int n = j >> 7, al = j & 127;
        if (al < na) {
            float4 g  = s_gt[n];
            float4 p  = s_pd[al];
            float2 ap = s_anc[al];
            float parea = (p.z - p.x) * (p.w - p.y + EPSF);
            float iou = iou_f(g, s_ga[n], p, parea);
            float o2 = iou * iou;
            float dmin = fminf(fminf(ap.x - g.x, ap.y - g.y),
                               fminf(g.z - ap.x, g.w - ap.y));
            float sc = s_sc[al*84 + s_lab[n]];
            float m = (dmin > EPSF) ? sc * o2*o2*o2 : 0.f;
            g_metrics[((long)(b*NG + n))*NA + a0 + al] = m;
        }
    }
}

// ---------------------------------------------------------------------------
// 2) top-13 per (b,n) with JAX tie-break (max value, then min index).
//    At winners: metric>0 with in-mask=1 implies align == metric exactly;
//    recompute overlap + in-mask only for the 13 winners.
// ---------------------------------------------------------------------------
__global__ void k_topk(const float* __restrict__ mask_gt,
                       const float4* __restrict__ pd_bbox,
                       const float2* __restrict__ anc,
                       const float4* __restrict__ gt_bbox) {
    __shared__ float s_m[NA];
    __shared__ float s_rv[8];
    __shared__ int   s_ri[8];
    __shared__ float s_wv[TK];
    __shared__ int   s_wi[TK];

    int n = blockIdx.x, b = blockIdx.y;
    int row = b*NG + n;
    int tid = threadIdx.x;

    if (mask_gt[row] <= 0.f) {             // masked gt: no entries at all
        if (tid < TK) g_tk_idx[row*TK + tid] = -1;
        return;
    }

    const float4* m4 = (const float4*)(g_metrics + (long)row*NA);
    for (int i = tid; i < NA/4; i += 256) {
        float4 v = m4[i];
        *(float4*)&s_m[i*4] = v;
    }
    __syncthreads();

    int lane = tid & 31, wid = tid >> 5;
    for (int k = 0; k < TK; k++) {
        float bv = -1.f; int bi = NA;
        for (int i = tid; i < NA; i += 256) {
            float v = s_m[i];
            if (v > bv) { bv = v; bi = i; }   // ascending i: keeps smallest idx on tie
        }
        #pragma unroll
        for (int off = 16; off; off >>= 1) {
            float ov = __shfl_down_sync(0xffffffffu, bv, off);
            int   oi = __shfl_down_sync(0xffffffffu, bi, off);
            if (ov > bv || (ov == bv && oi < bi)) { bv = ov; bi = oi; }
        }
        if (lane == 0) { s_rv[wid] = bv; s_ri[wid] = bi; }
        __syncthreads();
        if (tid == 0) {
            float Bv = s_rv[0]; int Bi = s_ri[0];
            #pragma unroll
            for (int w = 1; w < 8; w++)
                if (s_rv[w] > Bv || (s_rv[w] == Bv && s_ri[w] < Bi)) { Bv = s_rv[w]; Bi = s_ri[w]; }
            s_wv[k] = Bv; s_wi[k] = Bi;
            s_m[Bi] = -1.f;
        }
        __syncthreads();
    }

    if (tid < TK) {
        int   i = s_wi[tid];
        float v = s_wv[tid];
        float4 g  = gt_bbox[row];
        float4 p  = pd_bbox[b*NA + i];
        float2 ap = anc[i];
        float garea = (g.z - g.x)*(g.w - g.y + EPSF);
        float parea = (p.z - p.x)*(p.w - p.y + EPSF);
        float iou = iou_f(g, garea, p, parea);
        float dmin = fminf(fminf(ap.x - g.x, ap.y - g.y),
                           fminf(g.z - ap.x, g.w - ap.y));
        bool ok = dmin > EPSF;               // mask_in_gts at the winner
        g_tk_idx[row*TK + tid]   = ok ? i : -1;
        g_tk_align[row*TK + tid] = v;        // == align_metric when ok
        g_tk_ovl[row*TK + tid]   = iou;
    }
}

// ---------------------------------------------------------------------------
// 3) sparse resolution
// ---------------------------------------------------------------------------
__global__ void k_init() {
    int gid = blockIdx.x*256 + threadIdx.x;
    if (gid < BS*NA) { g_count[gid] = 0; g_cand_n[gid] = -1; }
    if (gid < BS*NG) { g_pos_align[gid] = 0u; g_pos_ovl[gid] = 0u; }
}

__global__ void k_scatter() {
    int gid = blockIdx.x*256 + threadIdx.x;
    if (gid >= BS*NG*TK) return;
    int idx = g_tk_idx[gid];
    if (idx >= 0) {
        int b = gid / (NG*TK);
        int n = (gid / TK) % NG;
        int p = b*NA + idx;
        atomicAdd(&g_count[p], 1);
        // benign races here: anchors with count>1 are fully rewritten in k_resolve
        g_cand_n[p]     = n;
        g_cand_align[p] = g_tk_align[gid];
        g_cand_ovl[p]   = g_tk_ovl[gid];
    }
}

// anchors claimed by >1 gt: reassign to argmax-overlap gt (first max on tie,
// over ALL n like the reference), recompute align = score * iou^6 there.
__global__ void k_resolve(const float* __restrict__ pd_scores,
                          const float4* __restrict__ pd_bbox,
                          const int* __restrict__ gt_labels,
                          const float4* __restrict__ gt_bbox) {
    __shared__ float4 s_gt[NG];
    __shared__ float  s_ga[NG];
    __shared__ int    s_lab[NG];
    int b = blockIdx.y;
    int tid = threadIdx.x;
    if (tid < NG) {
        float4 g = gt_bbox[b*NG + tid];
        s_gt[tid]  = g;
        s_ga[tid]  = (g.z - g.x)*(g.w - g.y + EPSF);
        s_lab[tid] = gt_labels[b*NG + tid];
    }
    __syncthreads();
    int a = blockIdx.x*256 + tid;
    if (a >= NA) return;
    int p = b*NA + a;
    if (g_count[p] > 1) {
        float4 pb = pd_bbox[b*NA + a];
        float parea = (pb.z - pb.x)*(pb.w - pb.y + EPSF);
        float bv = -1.f; int bn = 0;
        #pragma unroll 4
        for (int n = 0; n < NG; n++) {
            float v = iou_f(s_gt[n], s_ga[n], pb, parea);
            if (v > bv) { bv = v; bn = n; }
        }
        float sc = pd_scores[((long)b*NA + a)*NC + s_lab[bn]];
        float o2 = bv*bv;
        g_cand_n[p]     = bn;
        g_cand_ovl[p]   = bv;
        g_cand_align[p] = sc * o2*o2*o2;
    }
}

__global__ void k_pos() {
    int gid = blockIdx.x*256 + threadIdx.x;
    if (gid >= BS*NA) return;
    int n = g_cand_n[gid];
    if (n >= 0) {
        int b = gid / NA;
        atomicMax(&g_pos_align[b*NG + n], __float_as_uint(g_cand_align[gid]));
        atomicMax(&g_pos_ovl[b*NG + n],   __float_as_uint(g_cand_ovl[gid]));
    }
}

// ---------------------------------------------------------------------------
// 4) outputs. NOTE: reference writes gt[b, 0] labels/boxes even for non-fg
//    anchors (target_gt_idx defaults to 0); only target_scores is fg-masked.
// ---------------------------------------------------------------------------
__global__ void k_out1(const int* __restrict__ gt_labels,
                       const float4* __restrict__ gt_bbox,
                       float* __restrict__ out) {
    int gid = blockIdx.x*256 + threadIdx.x;
    if (gid >= BS*NA) return;
    int b = gid / NA;
    int cn = g_cand_n[gid];
    bool fg = cn >= 0;
    int tgt = fg ? cn : 0;
    int lab = gt_labels[b*NG + tgt];
    float4 box = gt_bbox[b*NG + tgt];
    float norm = 0.f;
    if (fg) {
        float pa = __uint_as_float(g_pos_align[b*NG + cn]);
        float po = __uint_as_float(g_pos_ovl[b*NG + cn]);
        norm = g_cand_align[gid] * po / (pa + EPSF);
    }
    out[OFF_LAB + gid] = (float)lab;
    ((float4*)(out + OFF_BOX))[gid] = box;
    out[OFF_FG  + gid] = fg ? 1.f : 0.f;
    out[OFF_TGT + gid] = (float)tgt;
    g_norm[gid]   = norm;
    g_labsel[gid] = fg ? lab : -1;
}

__global__ void k_out2(float* __restrict__ out) {
    int f4 = blockIdx.x*256 + threadIdx.x;   // grid sized exactly BS*NA*20
    int ba = f4 / 20;
    int c0 = (f4 % 20) * 4;
    int lab = g_labsel[ba];
    float nv = g_norm[ba];
    float4 v;
    v.x = (c0 + 0 == lab) ? nv : 0.f;
    v.y = (c0 + 1 == lab) ? nv : 0.f;
    v.z = (c0 + 2 == lab) ? nv : 0.f;
    v.w = (c0 + 3 == lab) ? nv : 0.f;
    ((float4*)(out + OFF_SCR))[f4] = v;
}

// ---------------------------------------------------------------------------
extern "C" void kernel_launch(void* const* d_in, const int* in_sizes, int n_in,
                              void* d_out, int out_size) {
    const float*  pd_scores = (const float*)d_in[0];
    const float4* pd_bbox   = (const float4*)d_in[1];
    const float2* anc       = (const float2*)d_in[2];
    const int*    gt_labels = (const int*)d_in[3];
    const float4* gt_bbox   = (const float4*)d_in[4];
    const float*  mask_gt   = (const float*)d_in[5];
    float* out = (float*)d_out;
    (void)in_sizes; (void)n_in; (void)out_size;

    k_init<<<(BS*NA + 255)/256, 256>>>();

    dim3 gF((NA + 127)/128, BS);
    k_metric<<<gF, 256>>>(pd_scores, pd_bbox, anc, gt_labels, gt_bbox);

    dim3 gK(NG, BS);
    k_topk<<<gK, 256>>>(mask_gt, pd_bbox, anc, gt_bbox);

    k_scatter<<<(BS*NG*TK + 255)/256, 256>>>();

    dim3 gR((NA + 255)/256, BS);
    k_resolve<<<gR, 256>>>(pd_scores, pd_bbox, gt_labels, gt_bbox);

    k_pos<<<(BS*NA + 255)/256, 256>>>();
    k_out1<<<(BS*NA + 255)/256, 256>>>(gt_labels, gt_bbox, out);
    k_out2<<<(BS*NA*20 + 255)/256, 256>>>(out);
}

// round 2
// speedup vs baseline: 1.6753x; 1.6753x over previous
#include <cuda_runtime.h>

#define BS 32
#define NA 8400
#define NC 80
#define NG 48
#define TK 13
#define EPSF 1e-9f
#define CAP 1024          // provable max positives per (b,n): area<=0.0906*8400=761

// output layout (floats), concatenated in reference return order
#define OFF_LAB 0
#define OFF_BOX (BS*NA)                 // 268800
#define OFF_SCR (OFF_BOX + BS*NA*4)     // 1344000
#define OFF_FG  (OFF_SCR + BS*NA*NC)    // 22848000
#define OFF_TGT (OFF_FG + BS*NA)        // 23116800

// scratch (device globals)
__device__ int                g_cnt[BS*NG];
__device__ unsigned long long g_list[BS*NG*CAP];   // packed (val_bits<<32)|(65535-idx)
__device__ int      g_count[BS*NA];
__device__ int      g_cand_n[BS*NA];
__device__ float    g_cand_align[BS*NA];
__device__ float    g_cand_ovl[BS*NA];
__device__ unsigned g_pos_align[BS*NG];
__device__ unsigned g_pos_ovl[BS*NG];
__device__ float    g_norm[BS*NA];
__device__ int      g_labsel[BS*NA];

__device__ __forceinline__ float iou_f(float4 g, float garea, float4 p, float parea) {
    float iw = fminf(g.z, p.z) - fmaxf(g.x, p.x); iw = fmaxf(iw, 0.f);
    float ih = fminf(g.w, p.w) - fmaxf(g.y, p.y); ih = fmaxf(ih, 0.f);
    float inter = iw * ih;
    float uni = garea + parea - inter + EPSF;
    return inter / uni;
}

// ---------------------------------------------------------------------------
// 0) zero the scratch that must be clean each call
// ---------------------------------------------------------------------------
__global__ void k_init() {
    int gid = blockIdx.x*256 + threadIdx.x;
    if (gid < BS*NA) { g_count[gid] = 0; g_cand_n[gid] = -1; }
    if (gid < BS*NG) { g_pos_align[gid] = 0u; g_pos_ovl[gid] = 0u; g_cnt[gid] = 0; }
}

// ---------------------------------------------------------------------------
// 1) sparse metric: in-box test first (98% early-out), then IoU, then a single
//    gathered score load; append positives to per-row candidate list.
// ---------------------------------------------------------------------------
__global__ void k_metric(const float* __restrict__ pd_scores,
                         const float4* __restrict__ pd_bbox,
                         const float2* __restrict__ anc,
                         const int* __restrict__ gt_labels,
                         const float4* __restrict__ gt_bbox) {
    __shared__ float4 s_pd[128];
    __shared__ float2 s_anc[128];
    __shared__ float  s_pa[128];
    __shared__ float4 s_gt[NG];
    __shared__ float  s_ga[NG];
    __shared__ int    s_lab[NG];

    int b  = blockIdx.y;
    int a0 = blockIdx.x * 128;
    int na = min(128, NA - a0);
    int tid = threadIdx.x;

    if (tid < NG) {
        float4 g = gt_bbox[b*NG + tid];
        s_gt[tid]  = g;
        s_ga[tid]  = (g.z - g.x) * (g.w - g.y + EPSF);
        s_lab[tid] = gt_labels[b*NG + tid];
    }
    for (int i = tid; i < na; i += 256) {
        float4 p = pd_bbox[b*NA + a0 + i];
        s_pd[i]  = p;
        s_pa[i]  = (p.z - p.x) * (p.w - p.y + EPSF);
        s_anc[i] = anc[a0 + i];
    }
    __syncthreads();

    for (int j = tid; j < NG*128; j += 256) {
        int n = j >> 7, al = j & 127;
        if (al >= na) continue;
        float4 g  = s_gt[n];
        float2 ap = s_anc[al];
        float dmin = fminf(fminf(ap.x - g.x, ap.y - g.y),
                           fminf(g.z - ap.x, g.w - ap.y));
        if (dmin > EPSF) {
            float iou = iou_f(g, s_ga[n], s_pd[al], s_pa[al]);
            if (iou > 0.f) {
                int a = a0 + al;
                float sc = __ldg(&pd_scores[(b*NA + a)*NC + s_lab[n]]);
                float o2 = iou * iou;
                float m  = sc * o2*o2*o2;
                if (m > 0.f) {
                    int row = b*NG + n;
                    int pos = atomicAdd(&g_cnt[row], 1);
                    if (pos < CAP) {
                        g_list[row*CAP + pos] =
                            ((unsigned long long)__float_as_uint(m) << 32)
                            | (unsigned)(65535 - a);
                    }
                }
            }
        }
    }
}

// ---------------------------------------------------------------------------
// 2) top-13 per (b,n) over the sparse list (warp per row) + fused scatter.
//    Packed-key max = (larger value, then smaller anchor index) = JAX tie-break.
//    If fewer than 13 positives: fill with smallest-index zero-metric anchors.
// ---------------------------------------------------------------------------
__global__ void k_topk_scatter(const float* __restrict__ mask_gt,
                               const float4* __restrict__ pd_bbox,
                               const float2* __restrict__ anc,
                               const float4* __restrict__ gt_bbox) {
    __shared__ unsigned long long s_list[4][CAP];   // 32 KB
    __shared__ int   s_win[4][TK];
    __shared__ float s_val[4][TK];

    int lane = threadIdx.x & 31;
    int w    = threadIdx.x >> 5;
    int row  = blockIdx.x * 4 + w;
    if (row >= BS*NG) return;
    int b = row / NG, n = row % NG;

    if (mask_gt[row] <= 0.f) return;   // masked gt contributes nothing

    int cnt = min(g_cnt[row], CAP);
    for (int i = lane; i < cnt; i += 32) s_list[w][i] = g_list[row*CAP + i];
    __syncwarp();

    int picks = 0;
    for (int k = 0; k < TK; k++) {
        unsigned long long bv = 0ull; int bi = -1;
        for (int i = lane; i < cnt; i += 32) {
            unsigned long long v = s_list[w][i];
            if (v > bv) { bv = v; bi = i; }
        }
        #pragma unroll
        for (int off = 16; off; off >>= 1) {
            unsigned long long ov = __shfl_xor_sync(0xffffffffu, bv, off);
            int oi = __shfl_xor_sync(0xffffffffu, bi, off);
            if (ov > bv) { bv = ov; bi = oi; }
        }
        if (bv == 0ull) break;
        if (lane == 0) {
            s_win[w][k] = 65535 - (int)(bv & 0xFFFFull);
            s_val[w][k] = __uint_as_float((unsigned)(bv >> 32));
            s_list[w][bi] = 0ull;
        }
        picks++;
        __syncwarp();
    }

    // fill remaining slots with smallest-index zero-metric anchors
    if (lane == 0 && picks < TK) {
        int k = picks, a = 0;
        while (k < TK) {
            bool used = false;
            for (int t = 0; t < picks; t++) if (s_win[w][t] == a) { used = true; break; }
            if (!used) { s_win[w][k] = a; s_val[w][k] = 0.f; k++; }
            a++;
        }
    }
    __syncwarp();

    if (lane < TK) {
        int   idx = s_win[w][lane];
        float val = s_val[w][lane];
        float4 g  = gt_bbox[row];
        float2 ap = anc[idx];
        float dmin = fminf(fminf(ap.x - g.x, ap.y - g.y),
                           fminf(g.z - ap.x, g.w - ap.y));
        if (dmin > EPSF) {                 // mask_in_gts at the winner
            float4 p = pd_bbox[b*NA + idx];
            float garea = (g.z - g.x)*(g.w - g.y + EPSF);
            float parea = (p.z - p.x)*(p.w - p.y + EPSF);
            float iou = iou_f(g, garea, p, parea);
            int pp = b*NA + idx;
            atomicAdd(&g_count[pp], 1);
            // benign race: anchors with count>1 fully rewritten in k_resolve
            g_cand_n[pp]     = n;
            g_cand_align[pp] = val;
            g_cand_ovl[pp]   = iou;
        }
    }
}

// ---------------------------------------------------------------------------
// 3) anchors claimed by >1 gt: reassign to argmax-overlap gt over ALL n
// ---------------------------------------------------------------------------
__global__ void k_resolve(const float* __restrict__ pd_scores,
                          const float4* __restrict__ pd_bbox,
                          const int* __restrict__ gt_labels,
                          const float4* __restrict__ gt_bbox) {
    __shared__ float4 s_gt[NG];
    __shared__ float  s_ga[NG];
    __shared__ int    s_lab[NG];
    int b = blockIdx.y;
    int tid = threadIdx.x;
    if (tid < NG) {
        float4 g = gt_bbox[b*NG + tid];
        s_gt[tid]  = g;
        s_ga[tid]  = (g.z - g.x)*(g.w - g.y + EPSF);
        s_lab[tid] = gt_labels[b*NG + tid];
    }
    __syncthreads();
    int a = blockIdx.x*256 + tid;
    if (a >= NA) return;
    int p = b*NA + a;
    if (g_count[p] > 1) {
        float4 pb = pd_bbox[b*NA + a];
        float parea = (pb.z - pb.x)*(pb.w - pb.y + EPSF);
        float bv = -1.f; int bn = 0;
        #pragma unroll 4
        for (int n = 0; n < NG; n++) {
            float v = iou_f(s_gt[n], s_ga[n], pb, parea);
            if (v > bv) { bv = v; bn = n; }
        }
        float sc = pd_scores[(b*NA + a)*NC + s_lab[bn]];
        float o2 = bv*bv;
        g_cand_n[p]     = bn;
        g_cand_ovl[p]   = bv;
        g_cand_align[p] = sc * o2*o2*o2;
    }
}

__global__ void k_pos() {
    int gid = blockIdx.x*256 + threadIdx.x;
    if (gid >= BS*NA) return;
    int n = g_cand_n[gid];
    if (n >= 0) {
        int b = gid / NA;
        atomicMax(&g_pos_align[b*NG + n], __float_as_uint(g_cand_align[gid]));
        atomicMax(&g_pos_ovl[b*NG + n],   __float_as_uint(g_cand_ovl[gid]));
    }
}

// ---------------------------------------------------------------------------
// 4) outputs
// ---------------------------------------------------------------------------
__global__ void k_out1(const int* __restrict__ gt_labels,
                       const float4* __restrict__ gt_bbox,
                       float* __restrict__ out) {
    int gid = blockIdx.x*256 + threadIdx.x;
    if (gid >= BS*NA) return;
    int b = gid / NA;
    int cn = g_cand_n[gid];
    bool fg = cn >= 0;
    int tgt = fg ? cn : 0;
    int lab = gt_labels[b*NG + tgt];
    float4 box = gt_bbox[b*NG + tgt];
    float norm = 0.f;
    if (fg) {
        float pa = __uint_as_float(g_pos_align[b*NG + cn]);
        float po = __uint_as_float(g_pos_ovl[b*NG + cn]);
        norm = g_cand_align[gid] * po / (pa + EPSF);
    }
    out[OFF_LAB + gid] = (float)lab;
    ((float4*)(out + OFF_BOX))[gid] = box;
    out[OFF_FG  + gid] = fg ? 1.f : 0.f;
    out[OFF_TGT + gid] = (float)tgt;
    g_norm[gid]   = norm;
    g_labsel[gid] = fg ? lab : -1;
}

__global__ void k_out2(float* __restrict__ out) {
    int f4 = blockIdx.x*256 + threadIdx.x;   // grid sized exactly BS*NA*20
    int ba = f4 / 20;
    int c0 = (f4 % 20) * 4;
    int lab = g_labsel[ba];
    float nv = g_norm[ba];
    float4 v;
    v.x = (c0 + 0 == lab) ? nv : 0.f;
    v.y = (c0 + 1 == lab) ? nv : 0.f;
    v.z = (c0 + 2 == lab) ? nv : 0.f;
    v.w = (c0 + 3 == lab) ? nv : 0.f;
    ((float4*)(out + OFF_SCR))[f4] = v;
}

// ---------------------------------------------------------------------------
extern "C" void kernel_launch(void* const* d_in, const int* in_sizes, int n_in,
                              void* d_out, int out_size) {
    const float*  pd_scores = (const float*)d_in[0];
    const float4* pd_bbox   = (const float4*)d_in[1];
    const float2* anc       = (const float2*)d_in[2];
    const int*    gt_labels = (const int*)d_in[3];
    const float4* gt_bbox   = (const float4*)d_in[4];
    const float*  mask_gt   = (const float*)d_in[5];
    float* out = (float*)d_out;
    (void)in_sizes; (void)n_in; (void)out_size;

    k_init<<<(BS*NA + 255)/256, 256>>>();

    dim3 gF((NA + 127)/128, BS);
    k_metric<<<gF, 256>>>(pd_scores, pd_bbox, anc, gt_labels, gt_bbox);

    k_topk_scatter<<<(BS*NG + 3)/4, 128>>>(mask_gt, pd_bbox, anc, gt_bbox);

    dim3 gR((NA + 255)/256, BS);
    k_resolve<<<gR, 256>>>(pd_scores, pd_bbox, gt_labels, gt_bbox);

    k_pos<<<(BS*NA + 255)/256, 256>>>();
    k_out1<<<(BS*NA + 255)/256, 256>>>(gt_labels, gt_bbox, out);
    k_out2<<<(BS*NA*20 + 255)/256, 256>>>(out);
}

// round 3
// speedup vs baseline: 1.8964x; 1.1320x over previous
#include <cuda_runtime.h>

#define BS 32
#define NA 8400
#define NC 80
#define NG 48
#define TK 13
#define EPSF 1e-9f
#define CAP 1024
#define GB 16
#define NBIN (GB*GB)
#define MAXMULTI (BS*NG*TK)

#define OFF_LAB 0
#define OFF_BOX (BS*NA)
#define OFF_SCR (OFF_BOX + BS*NA*4)
#define OFF_FG  (OFF_SCR + BS*NA*NC)
#define OFF_TGT (OFF_FG + BS*NA)

__device__ int      g_bin_cnt[NBIN];
__device__ int      g_bin_fill[NBIN];
__device__ int      g_bin_off[NBIN+1];
__device__ int      g_bin_anchor[NA];
__device__ float2   g_anc_sorted[NA];
__device__ int      g_count[BS*NA];
__device__ int      g_cand_n[BS*NA];
__device__ float    g_cand_align[BS*NA];
__device__ float    g_cand_ovl[BS*NA];
__device__ unsigned g_pos_align[BS*NG];
__device__ unsigned g_pos_ovl[BS*NG];
__device__ float    g_norm[BS*NA];
__device__ int      g_labsel[BS*NA];
__device__ int      g_multi[MAXMULTI];
__device__ int      g_multi_cnt;

__device__ __forceinline__ float iou_f(float4 g, float garea, float4 p, float parea) {
    float iw = fminf(g.z, p.z) - fmaxf(g.x, p.x); iw = fmaxf(iw, 0.f);
    float ih = fminf(g.w, p.w) - fmaxf(g.y, p.y); ih = fmaxf(ih, 0.f);
    float inter = iw * ih;
    float uni = garea + parea - inter + EPSF;
    return inter / uni;
}

__device__ __forceinline__ int binclamp(float v) {
    int x = (int)(v * GB);
    return min(max(x, 0), GB - 1);
}

__global__ void k_init() {
    int gid = blockIdx.x*256 + threadIdx.x;
    if (gid < BS*NA) { g_count[gid] = 0; g_cand_n[gid] = -1; }
    if (gid < BS*NG) { g_pos_align[gid] = 0u; g_pos_ovl[gid] = 0u; }
    if (gid < NBIN)  { g_bin_cnt[gid] = 0; g_bin_fill[gid] = 0; }
    if (gid == 0)    g_multi_cnt = 0;
}

__global__ void k_bincount(const float2* __restrict__ anc) {
    int a = blockIdx.x*256 + threadIdx.x;
    if (a >= NA) return;
    float2 p = anc[a];
    atomicAdd(&g_bin_cnt[binclamp(p.y)*GB + binclamp(p.x)], 1);
}

__global__ void k_binscan() {
    __shared__ int s[NBIN];
    int t = threadIdx.x;
    s[t] = g_bin_cnt[t];
    __syncthreads();
    for (int off = 1; off < NBIN; off <<= 1) {
        int v = (t >= off) ? s[t - off] : 0;
        __syncthreads();
        s[t] += v;
        __syncthreads();
    }
    g_bin_off[t + 1] = s[t];
    if (t == 0) g_bin_off[0] = 0;
}

__global__ void k_binfill(const float2* __restrict__ anc) {
    int a = blockIdx.x*256 + threadIdx.x;
    if (a >= NA) return;
    float2 p = anc[a];
    int bin = binclamp(p.y)*GB + binclamp(p.x);
    int pos = g_bin_off[bin] + atomicAdd(&g_bin_fill[bin], 1);
    g_bin_anchor[pos] = a;
    g_anc_sorted[pos] = p;
}

// fused sparse metric + top-13 + scatter; block = one (b,n) row
__global__ void k_assign(const float* __restrict__ pd_scores,
                         const float4* __restrict__ pd_bbox,
                         const float2* __restrict__ anc,
                         const float* __restrict__ mask_gt,
                         const int* __restrict__ gt_labels,
                         const float4* __restrict__ gt_bbox) {
    __shared__ unsigned long long s_list[CAP];
    __shared__ int   s_cnt;
    __shared__ int   s_win[TK];
    __shared__ float s_val[TK];
    __shared__ int   s_picks;

    int row = blockIdx.x;
    int b = row / NG, n = row % NG;
    int tid = threadIdx.x;

    if (mask_gt[row] <= 0.f) return;

    float4 g = gt_bbox[row];
    float garea = (g.z - g.x) * (g.w - g.y + EPSF);
    int lab = gt_labels[row];
    if (tid == 0) s_cnt = 0;
    __syncthreads();

    int bx0 = binclamp(g.x), bx1 = binclamp(g.z);
    int by0 = binclamp(g.y), by1 = binclamp(g.w);

    for (int by = by0; by <= by1; by++) {
        int s0 = g_bin_off[by*GB + bx0];
        int s1 = g_bin_off[by*GB + bx1 + 1];
        for (int i = s0 + tid; i < s1; i += 128) {
            float2 ap = g_anc_sorted[i];
            float dmin = fminf(fminf(ap.x - g.x, ap.y - g.y),
                               fminf(g.z - ap.x, g.w - ap.y));
            if (dmin > EPSF) {
                int a = g_bin_anchor[i];
                float4 p = pd_bbox[b*NA + a];
                float parea = (p.z - p.x) * (p.w - p.y + EPSF);
                float iou = iou_f(g, garea, p, parea);
                if (iou > 0.f) {
                    float sc = __ldg(&pd_scores[(b*NA + a)*NC + lab]);
                    float o2 = iou * iou;
                    float m  = sc * o2*o2*o2;
                    if (m > 0.f) {
                        int pos = atomicAdd(&s_cnt, 1);
                        if (pos < CAP)
                            s_list[pos] = ((unsigned long long)__float_as_uint(m) << 32)
                                        | (unsigned)(65535 - a);
                    }
                }
            }
        }
    }
    __syncthreads();
    int cnt = min(s_cnt, CAP);

    if (tid < 32) {
        int picks = 0;
        for (int k = 0; k < TK; k++) {
            unsigned long long bv = 0ull; int bi = -1;
            for (int i = tid; i < cnt; i += 32) {
                unsigned long long v = s_list[i];
                if (v > bv) { bv = v; bi = i; }
            }
            #pragma unroll
            for (int off = 16; off; off >>= 1) {
                unsigned long long ov = __shfl_xor_sync(0xffffffffu, bv, off);
                int oi = __shfl_xor_sync(0xffffffffu, bi, off);
                if (ov > bv) { bv = ov; bi = oi; }
            }
            if (bv == 0ull) break;
            if (tid == 0) {
                s_win[k] = 65535 - (int)(bv & 0xFFFFull);
                s_val[k] = __uint_as_float((unsigned)(bv >> 32));
                s_list[bi] = 0ull;
            }
            picks++;
            __syncwarp();
        }
        if (tid == 0) {
            s_picks = picks;
            int k = picks, a = 0;
            while (k < TK) {
                bool used = false;
                for (int t = 0; t < picks; t++) if (s_win[t] == a) { used = true; break; }
                if (!used) { s_win[k] = a; s_val[k] = 0.f; k++; }
                a++;
            }
        }
        __syncwarp();

        if (tid < TK) {
            int   idx = s_win[tid];
            float val = s_val[tid];
            bool claim;
            float iou = 0.f;
            float4 p;
            if (tid < s_picks) {
                claim = true;                       // m>0 implies in-box
                p = pd_bbox[b*NA + idx];
            } else {
                float2 ap = anc[idx];               // filler: in-box test required
                float dmin = fminf(fminf(ap.x - g.x, ap.y - g.y),
                                   fminf(g.z - ap.x, g.w - ap.y));
                claim = dmin > EPSF;
                if (claim) p = pd_bbox[b*NA + idx];
            }
            if (claim) {
                float parea = (p.z - p.x)*(p.w - p.y + EPSF);
                iou = iou_f(g, garea, p, parea);
                int pp = b*NA + idx;
                int old = atomicAdd(&g_count[pp], 1);
                if (old > 0) {
                    int mp = atomicAdd(&g_multi_cnt, 1);
                    if (mp < MAXMULTI) g_multi[mp] = pp;
                }
                g_cand_n[pp]     = n;
                g_cand_align[pp] = val;
                g_cand_ovl[pp]   = iou;
            }
        }
    }
}

// sparse resolve over the compact multi-claim list only
__global__ void k_resolve(const float* __restrict__ pd_scores,
                          const float4* __restrict__ pd_bbox,
                          const int* __restrict__ gt_labels,
                          const float4* __restrict__ gt_bbox) {
    int gid = blockIdx.x*256 + threadIdx.x;
    int mc = min(g_multi_cnt, MAXMULTI);
    if (gid >= mc) return;
    int p = g_multi[gid];
    int b = p / NA, a = p % NA;
    float4 pb = pd_bbox[p];
    float parea = (pb.z - pb.x)*(pb.w - pb.y + EPSF);
    float bv = -1.f; int bn = 0;
    for (int n = 0; n < NG; n++) {
        float4 gg = gt_bbox[b*NG + n];
        float ga = (gg.z - gg.x)*(gg.w - gg.y + EPSF);
        float v = iou_f(gg, ga, pb, parea);
        if (v > bv) { bv = v; bn = n; }
    }
    float sc = pd_scores[(b*NA + a)*NC + gt_labels[b*NG + bn]];
    float o2 = bv*bv;
    g_cand_n[p]     = bn;
    g_cand_ovl[p]   = bv;
    g_cand_align[p] = sc * o2*o2*o2;
}

__global__ void k_pos() {
    int gid = blockIdx.x*256 + threadIdx.x;
    if (gid >= BS*NA) return;
    int n = g_cand_n[gid];
    if (n >= 0) {
        int b = gid / NA;
        atomicMax(&g_pos_align[b*NG + n], __float_as_uint(g_cand_align[gid]));
        atomicMax(&g_pos_ovl[b*NG + n],   __float_as_uint(g_cand_ovl[gid]));
    }
}

__global__ void k_out1(const int* __restrict__ gt_labels,
                       const float4* __restrict__ gt_bbox,
                       float* __restrict__ out) {
    int gid = blockIdx.x*256 + threadIdx.x;
    if (gid >= BS*NA) return;
    int b = gid / NA;
    int cn = g_cand_n[gid];
    bool fg = cn >= 0;
    int tgt = fg ? cn : 0;
    int lab = gt_labels[b*NG + tgt];
    float4 box = gt_bbox[b*NG + tgt];
    float norm = 0.f;
    if (fg) {
        float pa = __uint_as_float(g_pos_align[b*NG + cn]);
        float po = __uint_as_float(g_pos_ovl[b*NG + cn]);
        norm = g_cand_align[gid] * po / (pa + EPSF);
    }
    out[OFF_LAB + gid] = (float)lab;
    ((float4*)(out + OFF_BOX))[gid] = box;
    out[OFF_FG  + gid] = fg ? 1.f : 0.f;
    out[OFF_TGT + gid] = (float)tgt;
    g_norm[gid]   = norm;
    g_labsel[gid] = fg ? lab : -1;
}

__global__ void k_out2(float* __restrict__ out) {
    int f4 = blockIdx.x*256 + threadIdx.x;
    int ba = f4 / 20;
    int c0 = (f4 % 20) * 4;
    int lab = g_labsel[ba];
    float nv = g_norm[ba];
    float4 v;
    v.x = (c0 + 0 == lab) ? nv : 0.f;
    v.y = (c0 + 1 == lab) ? nv : 0.f;
    v.z = (c0 + 2 == lab) ? nv : 0.f;
    v.w = (c0 + 3 == lab) ? nv : 0.f;
    ((float4*)(out + OFF_SCR))[f4] = v;
}

extern "C" void kernel_launch(void* const* d_in, const int* in_sizes, int n_in,
                              void* d_out, int out_size) {
    const float*  pd_scores = (const float*)d_in[0];
    const float4* pd_bbox   = (const float4*)d_in[1];
    const float2* anc       = (const float2*)d_in[2];
    const int*    gt_labels = (const int*)d_in[3];
    const float4* gt_bbox   = (const float4*)d_in[4];
    const float*  mask_gt   = (const float*)d_in[5];
    float* out = (float*)d_out;
    (void)in_sizes; (void)n_in; (void)out_size;

    k_init<<<(BS*NA + 255)/256, 256>>>();
    k_bincount<<<(NA + 255)/256, 256>>>(anc);
    k_binscan<<<1, 256>>>();
    k_binfill<<<(NA + 255)/256, 256>>>(anc);
    k_assign<<<BS*NG, 128>>>(pd_scores, pd_bbox, anc, mask_gt, gt_labels, gt_bbox);
    k_resolve<<<(MAXMULTI + 255)/256, 256>>>(pd_scores, pd_bbox, gt_labels, gt_bbox);
    k_pos<<<(BS*NA + 255)/256, 256>>>();
    k_out1<<<(BS*NA + 255)/256, 256>>>(gt_labels, gt_bbox, out);
    k_out2<<<(BS*NA*20 + 255)/256, 256>>>(out);
}